// round 16
// baseline (speedup 1.0000x reference)
#include <cuda_runtime.h>
#include <cuda_fp16.h>
#include <cstdint>

// Problem constants
#define Bq   1024
#define Nn   128
#define Dd   256
#define Hh   8
#define NB   2
#define NEGV (-1e9f)
#define CLIPV 10.0f
#define INV_SQRT_DH 0.17677669529663687f  // 1/sqrt(32)
#define INV_SQRT_D  0.0625f               // 1/sqrt(256)

#define ROWS_TOTAL (Bq * Nn)              // 131072
#define WSCALE     16.0f                  // W pre-scale (exact pow2)
#define WUNSCALE   0.0625f                // 1/16
#define WOC_SROWS  128                    // Woc rows cached in smem

// ---------------- scratch (device globals; no cudaMalloc allowed) ----------
__device__ float g_K   [Bq * Nn * Dd];   // [b][n][d]  (E@Wk)
__device__ float g_V   [Bq * Nn * Dd];   // [b][n][d]  (E@Wv)
__device__ float g_LK2 [Bq * Nn * Dd];   // [b][n][d]  (E@(Wlk@Wo^T))
__device__ float g_P   [Bq * Nn * Dd];   // [b][n][d]  (E@Ws_bot)
__device__ float g_Woc [Dd * Dd];        // Wo@Wc
__device__ float g_Wlk2[Dd * Dd];        // Wlk@Wo^T
__device__ int   g_mlp;                  // 1 if (W2,b2) nonzero -> general path

// fp16 2-way splits (x ~= h0+h1 to ~2^-22)
__device__ __half g_Es[2][ROWS_TOTAL * Dd];     // E splits
__device__ __half g_Wt[2][4][Dd * Dd];          // (16*W)^T splits [s][w][n][k]

// ================= helpers ==================================================
__device__ __forceinline__ uint32_t smem_u32(const void* p) {
    uint32_t a;
    asm("{ .reg .u64 t; cvta.to.shared.u64 t, %1; cvt.u32.u64 %0, t; }"
        : "=r"(a) : "l"(p));
    return a;
}
__device__ __forceinline__ void ldsm_x4(uint32_t* r, uint32_t addr) {
    asm volatile("ldmatrix.sync.aligned.m8n8.x4.shared.b16 {%0,%1,%2,%3}, [%4];"
        : "=r"(r[0]), "=r"(r[1]), "=r"(r[2]), "=r"(r[3]) : "r"(addr));
}
__device__ __forceinline__ void mma_fp16(float* c, const uint32_t* a, const uint32_t* b) {
    asm volatile("mma.sync.aligned.m16n8k16.row.col.f32.f16.f16.f32 "
        "{%0,%1,%2,%3}, {%4,%5,%6,%7}, {%8,%9}, {%0,%1,%2,%3};"
        : "+f"(c[0]), "+f"(c[1]), "+f"(c[2]), "+f"(c[3])
        : "r"(a[0]), "r"(a[1]), "r"(a[2]), "r"(a[3]), "r"(b[0]), "r"(b[1]));
}
__device__ __forceinline__ void cp_async16(uint32_t dst, const void* src) {
    asm volatile("cp.async.cg.shared.global [%0], [%1], 16;"
                 :: "r"(dst), "l"(src) : "memory");
}
#define CP_COMMIT() asm volatile("cp.async.commit_group;" ::: "memory")
#define CP_WAIT0()  asm volatile("cp.async.wait_group 0;" ::: "memory")

#define K3_ABUF(p) ((p) * 16384)
#define K3_BBUF(p) (32768 + (p) * 16384)
#define K3T_SMEM   65536

#define DOT4(u, v) ((u).x * (v).x + (u).y * (v).y + (u).z * (v).z + (u).w * (v).w)

// ---------------- k1: Woc = Wo@Wc ; Wlk2 = Wlk@Wo^T ; mlp-detect -----------
__global__ void k1_weights(const float* __restrict__ Wo,
                           const float* __restrict__ Wc,
                           const float* __restrict__ Wlk,
                           const float* __restrict__ W2,
                           const float* __restrict__ b2)
{
    int bid = blockIdx.x;
    int d = threadIdx.x;
    if (bid < 256) {               // Woc row bid
        float acc = 0.f;
        #pragma unroll 8
        for (int j = 0; j < Dd; j++) acc += Wo[bid * Dd + j] * Wc[j * Dd + d];
        g_Woc[bid * Dd + d] = acc;
    } else if (bid < 512) {        // Wlk2 row m: sum_j Wlk[m][j] * Wo[d][j]
        int m = bid - 256;
        __shared__ float lr[Dd];
        lr[d] = Wlk[m * Dd + d];
        __syncthreads();
        const float* Wod = Wo + (size_t)d * Dd;
        float a0 = 0.f, a1 = 0.f;
        #pragma unroll 8
        for (int j = 0; j < Dd; j += 2) {
            a0 += lr[j]     * Wod[j];
            a1 += lr[j + 1] * Wod[j + 1];
        }
        g_Wlk2[m * Dd + d] = a0 + a1;
    } else {                       // mlp-nonzero detect
        __shared__ int any;
        if (d == 0) any = 0;
        __syncthreads();
        int loc = 0;
        for (int i = d; i < Dd * Dd; i += blockDim.x) loc |= (W2[i] != 0.0f);
        loc |= (b2[d] != 0.0f);
        if (loc) atomicOr(&any, 1);
        __syncthreads();
        if (d == 0) g_mlp = any;
    }
}

// ---------------- k_split: fused E-split + W-split ---------------------------
__global__ void k_split(const float* __restrict__ E,
                        const float* __restrict__ Wk,
                        const float* __restrict__ Wv,
                        const float* __restrict__ Ws)
{
    const int bid = blockIdx.x;
    if (bid < 8192) {
        const size_t total = (size_t)ROWS_TOTAL * Dd;
        const size_t stride = (size_t)8192 * blockDim.x;
        for (size_t i = (size_t)bid * blockDim.x + threadIdx.x; i < total; i += stride) {
            float x = E[i];
            __half h0 = __float2half_rn(x);
            float r = x - __half2float(h0);
            __half h1 = __float2half_rn(r);
            g_Es[0][i] = h0; g_Es[1][i] = h1;
        }
    } else {
        const int idx = bid - 8192;
        const int w = idx & 3, n = idx >> 2, k = threadIdx.x;
        const float* src;
        if      (w == 0) src = Wk;
        else if (w == 1) src = Wv;
        else if (w == 2) src = g_Wlk2;
        else             src = Ws + Dd * Dd;
        float x = src[k * Dd + n] * WSCALE;
        __half h0 = __float2half_rn(x);
        float r = x - __half2float(h0);
        __half h1 = __float2half_rn(r);
        g_Wt[0][w][n * Dd + k] = h0;
        g_Wt[1][w][n * Dd + k] = h1;
    }
}

// ---------------- k3t: mma.sync fp16-2split GEMM, cp.async pipelined --------
__global__ void __launch_bounds__(256, 2) k3t_mma()
{
    extern __shared__ char smem[];
    const uint32_t sbase = smem_u32(smem);
    const int tid = threadIdx.x;
    const int warp = tid >> 5, lane = tid & 31;
    const int rowbase = blockIdx.x * 128;
    const int nbase   = blockIdx.y * 128;
    const int w       = blockIdx.z;

    float* out;
    if      (w == 0) out = g_K;
    else if (w == 1) out = g_V;
    else if (w == 2) out = g_LK2;
    else             out = g_P;

    const int wm = warp & 3;
    const int wn = warp >> 2;

    float acc[2][8][4] = {};

    uint32_t st_dst[8];
    const __half* st_src[8];
    #pragma unroll
    for (int it = 0; it < 8; it++) {
        int i = tid + it * 256;
        int reg = i >> 10, s = (i >> 9) & 1, row = (i >> 2) & 127, q = i & 3;
        uint32_t off = (uint32_t)(s * 8192 + row * 64 + ((q * 16) ^ ((row & 6) << 3)));
        if (reg == 0) {
            st_dst[it] = off;
            st_src[it] = &g_Es[s][(size_t)(rowbase + row) * Dd + q * 8];
        } else {
            st_dst[it] = 32768u + off;
            st_src[it] = &g_Wt[s][w][(size_t)(nbase + row) * Dd + q * 8];
        }
    }

    uint32_t a_off[2], a_mask[2];
    #pragma unroll
    for (int mb = 0; mb < 2; mb++) {
        int row = wm * 32 + mb * 16 + (lane & 15);
        a_off[mb]  = (uint32_t)(row * 64);
        a_mask[mb] = (uint32_t)(((row & 6) << 3) ^ ((lane >> 4) * 16));
    }
    uint32_t b_off[4], b_mask[4];
    #pragma unroll
    for (int p = 0; p < 4; p++) {
        int pr = lane >> 3;
        int nrow = wn * 64 + p * 16 + ((pr >> 1) << 3) + (lane & 7);
        b_off[p]  = (uint32_t)(nrow * 64);
        b_mask[p] = (uint32_t)(((nrow & 6) << 3) ^ ((pr & 1) * 16));
    }

    {
        const uint32_t abase = sbase + K3_ABUF(0);
        #pragma unroll
        for (int it = 0; it < 8; it++)
            cp_async16(abase + st_dst[it], st_src[it]);
        CP_COMMIT();
    }

    for (int c = 0; c < 8; c++) {
        CP_WAIT0();
        __syncthreads();

        if (c + 1 < 8) {
            const uint32_t abase = sbase + K3_ABUF((c + 1) & 1);
            const int kadv = (c + 1) * 32;
            #pragma unroll
            for (int it = 0; it < 8; it++)
                cp_async16(abase + st_dst[it], st_src[it] + kadv);
            CP_COMMIT();
        }

        const uint32_t Ab = sbase + K3_ABUF(c & 1);
        const uint32_t Bb = sbase + K3_BBUF(c & 1);

        #pragma unroll
        for (int ks = 0; ks < 2; ks++) {
            const uint32_t kx = (uint32_t)(ks * 32);
            uint32_t af[2][2][4];
            #pragma unroll
            for (int s = 0; s < 2; s++)
                #pragma unroll
                for (int mb = 0; mb < 2; mb++)
                    ldsm_x4(af[s][mb], Ab + s * 8192 + a_off[mb] + (kx ^ a_mask[mb]));
            #pragma unroll
            for (int p = 0; p < 4; p++) {
                uint32_t b0[4];
                ldsm_x4(b0, Bb + b_off[p] + (kx ^ b_mask[p]));
                #pragma unroll
                for (int sa = 0; sa < 2; sa++) {
                    mma_fp16(acc[0][2 * p],     af[sa][0], b0 + 0);
                    mma_fp16(acc[0][2 * p + 1], af[sa][0], b0 + 2);
                    mma_fp16(acc[1][2 * p],     af[sa][1], b0 + 0);
                    mma_fp16(acc[1][2 * p + 1], af[sa][1], b0 + 2);
                }
                uint32_t b1[4];
                ldsm_x4(b1, Bb + 8192 + b_off[p] + (kx ^ b_mask[p]));
                mma_fp16(acc[0][2 * p],     af[0][0], b1 + 0);
                mma_fp16(acc[0][2 * p + 1], af[0][0], b1 + 2);
                mma_fp16(acc[1][2 * p],     af[0][1], b1 + 0);
                mma_fp16(acc[1][2 * p + 1], af[0][1], b1 + 2);
            }
        }
        __syncthreads();
    }

    const int r0 = rowbase + wm * 32 + (lane >> 2);
    const int c0 = nbase + wn * 64 + (lane & 3) * 2;
    #pragma unroll
    for (int mb = 0; mb < 2; mb++)
        #pragma unroll
        for (int nb = 0; nb < 8; nb++) {
            float2 lo = make_float2(acc[mb][nb][0] * WUNSCALE, acc[mb][nb][1] * WUNSCALE);
            float2 hi = make_float2(acc[mb][nb][2] * WUNSCALE, acc[mb][nb][3] * WUNSCALE);
            *(float2*)(out + (size_t)(r0 + mb * 16)     * Dd + c0 + nb * 8) = lo;
            *(float2*)(out + (size_t)(r0 + mb * 16 + 8) * Dd + c0 + nb * 8) = hi;
        }
}

// ---------------- k4: persistent decode, 512 threads, 1 block/SM ------------
// L2-residency design: 1 block/SM (enforced by ~152KB smem) keeps the
// concurrent stream set (148 x 768KB = 113MB) inside L2. Half of Woc is
// cached in smem. Thread (bb = tid>>8, d = tid&255) owns one (batch, dim).
struct K4S {
    float q[NB][Dd];
    float heads[NB][Dd];          // also staging (q0-mean / t==0 E rows)
    float cc[NB][Nn][9];          // compat; reused as MLP scratch
    float pp[NB][Hh][Nn + 4];
    float ls[NB][Nn];
    int   list[NB][Nn];
    float sum[NB][Hh];
    int   sel[NB];
    int   cnt;
    float wocs[WOC_SROWS * Dd];   // Woc rows [0,128) in smem (128KB)
};

__device__ __forceinline__ void k4_fin_q(K4S& S, int bb, int d, int mlp,
                                         const float* __restrict__ W1,
                                         const float* __restrict__ b1,
                                         const float* __restrict__ W2,
                                         const float* __restrict__ b2)
{
    if (mlp) {
        float* hid = &S.cc[0][0][0];
        __syncthreads();
        float m1 = b1[d];
        #pragma unroll 8
        for (int k = 0; k < Dd; k++) m1 += S.q[bb][k] * W1[k * Dd + d];
        hid[bb * Dd + d] = fmaxf(m1, 0.0f);
        __syncthreads();
        float m2 = b2[d];
        #pragma unroll 8
        for (int k = 0; k < Dd; k++) m2 += hid[bb * Dd + k] * W2[k * Dd + d];
        __syncthreads();
        S.q[bb][d] = (S.q[bb][d] + m2) * INV_SQRT_DH;
    } else {
        S.q[bb][d] *= INV_SQRT_DH;
    }
    __syncthreads();
}

__global__ void k4_decode(const float* __restrict__ E,
                          const float* __restrict__ coords,
                          const float* __restrict__ Wc,
                          const float* __restrict__ Ws,
                          const float* __restrict__ Wph,
                          const float* __restrict__ W1,
                          const float* __restrict__ b1,
                          const float* __restrict__ W2,
                          const float* __restrict__ b2,
                          float* __restrict__ out)
{
    extern __shared__ char smem_raw[];
    K4S& S = *(K4S*)smem_raw;

    const int b0 = blockIdx.x * NB;
    const int tid = threadIdx.x;            // 0..511
    const int warp = tid >> 5, lane = tid & 31;
    const int wb  = warp >> 3;               // batch for row-dot phases
    const int wj0 = warp & 7;                // row start, stride 8
    const int bb  = tid >> 8;                // batch this thread owns
    const int d   = tid & 255;               // dim this thread owns
    const int mlp = g_mlp;

    // load Woc rows [0,128) into smem (one-time)
    for (int i = tid; i < WOC_SROWS * Dd; i += 512) S.wocs[i] = g_Woc[i];

    if (tid < Nn) {
        S.list[0][tid] = tid;
        S.list[1][tid] = tid;
    }
    if (tid == 0) S.cnt = Nn;

    // ---- prologue: q0 = mean_n(E)@Wc + Wph@Ws ------------------------------
    {
        float pcv = 0.f;
        #pragma unroll 8
        for (int k = 0; k < 2 * Dd; k++) pcv += Wph[k] * Ws[k * Dd + d];
        float s = 0.f;
        const float* Eb = E + (size_t)(b0 + bb) * Nn * Dd + d;
        #pragma unroll 8
        for (int n = 0; n < Nn; n++) s += Eb[n * Dd];
        S.heads[bb][d] = s * (1.0f / Nn);
        __syncthreads();
        float acc = pcv;
        #pragma unroll 8
        for (int k = 0; k < Dd; k++) acc += S.heads[bb][k] * Wc[k * Dd + d];
        __syncthreads();
        S.q[bb][d] = acc;
    }
    k4_fin_q(S, bb, d, mlp, W1, b1, W2, b2);

    const float* Kbase  = g_K   + (size_t)b0 * Nn * Dd;
    const float* Vbase  = g_V   + (size_t)b0 * Nn * Dd;
    const float* LKbase = g_LK2 + (size_t)b0 * Nn * Dd;

    float ll = 0.f, cost = 0.f;             // lane0 of warps 0 and 8
    float fx = 0.f, fy = 0.f, px = 0.f, py = 0.f;
    float fctx = 0.f;                        // per-thread (bb,d)

    for (int t = 0; t < Nn; t++) {
        const int cnt = S.cnt;

        {   // ---- compat: 8 warps per batch, 4 rows/iter --------------------
            const float4* q4 = (const float4*)S.q[wb];
            float4 qa = q4[lane], qb = q4[lane + 32];
            const float* Kb = Kbase + (size_t)wb * Nn * Dd;
            const int* lst = S.list[wb];
            for (int j = wj0; j < cnt; j += 32) {
                const int j1 = j + 8, j2 = j + 16, j3 = j + 24;
                const bool v1 = (j1 < cnt), v2 = (j2 < cnt), v3 = (j3 < cnt);
                const float4* R0 = (const float4*)(Kb + (size_t)lst[j] * Dd);
                const float4* R1 = (const float4*)(Kb + (size_t)lst[v1 ? j1 : j] * Dd);
                const float4* R2 = (const float4*)(Kb + (size_t)lst[v2 ? j2 : j] * Dd);
                const float4* R3 = (const float4*)(Kb + (size_t)lst[v3 ? j3 : j] * Dd);
                float4 x0 = R0[lane], x1 = R0[lane + 32];
                float4 y0 = R1[lane], y1 = R1[lane + 32];
                float4 z0 = R2[lane], z1 = R2[lane + 32];
                float4 u0 = R3[lane], u1 = R3[lane + 32];
                float alo = DOT4(x0, qa), ahi = DOT4(x1, qb);
                float blo = DOT4(y0, qa), bhi = DOT4(y1, qb);
                float clo = DOT4(z0, qa), chi = DOT4(z1, qb);
                float dlo = DOT4(u0, qa), dhi = DOT4(u1, qb);
                #pragma unroll
                for (int o = 1; o < 8; o <<= 1) {
                    alo += __shfl_xor_sync(0xffffffffu, alo, o);
                    ahi += __shfl_xor_sync(0xffffffffu, ahi, o);
                    blo += __shfl_xor_sync(0xffffffffu, blo, o);
                    bhi += __shfl_xor_sync(0xffffffffu, bhi, o);
                    clo += __shfl_xor_sync(0xffffffffu, clo, o);
                    chi += __shfl_xor_sync(0xffffffffu, chi, o);
                    dlo += __shfl_xor_sync(0xffffffffu, dlo, o);
                    dhi += __shfl_xor_sync(0xffffffffu, dhi, o);
                }
                if ((lane & 7) == 0) {
                    int hg = lane >> 3;
                    S.cc[wb][j][hg]     = alo;
                    S.cc[wb][j][4 + hg] = ahi;
                    if (v1) { S.cc[wb][j1][hg] = blo; S.cc[wb][j1][4 + hg] = bhi; }
                    if (v2) { S.cc[wb][j2][hg] = clo; S.cc[wb][j2][4 + hg] = chi; }
                    if (v3) { S.cc[wb][j3][hg] = dlo; S.cc[wb][j3][4 + hg] = dhi; }
                }
            }
        }
        __syncthreads();

        {   // ---- softmax: warp = (bb, h), single pass ----------------------
            const int sb = warp >> 3, h = warp & 7;
            float m = NEGV;
            for (int j = lane; j < cnt; j += 32) m = fmaxf(m, S.cc[sb][j][h]);
            #pragma unroll
            for (int o = 16; o; o >>= 1)
                m = fmaxf(m, __shfl_xor_sync(0xffffffffu, m, o));
            float s = 0.f;
            for (int j = lane; j < cnt; j += 32) {
                float e = expf(S.cc[sb][j][h] - m);
                S.pp[sb][h][j] = e;
                s += e;
            }
            #pragma unroll
            for (int o = 16; o; o >>= 1) s += __shfl_xor_sync(0xffffffffu, s, o);
            if (lane == 0) S.sum[sb][h] = s;
        }
        __syncthreads();

        {   // ---- heads: thread (bb,d), 4 accumulators ----------------------
            const int h = d >> 5;
            float a0 = 0.f, a1 = 0.f, a2 = 0.f, a3 = 0.f;
            const float* Vd = Vbase + (size_t)bb * Nn * Dd + d;
            const int* lst = S.list[bb];
            const float* pr = S.pp[bb][h];
            int j = 0;
            for (; j + 4 <= cnt; j += 4) {
                a0 += pr[j]     * Vd[(size_t)lst[j]     * Dd];
                a1 += pr[j + 1] * Vd[(size_t)lst[j + 1] * Dd];
                a2 += pr[j + 2] * Vd[(size_t)lst[j + 2] * Dd];
                a3 += pr[j + 3] * Vd[(size_t)lst[j + 3] * Dd];
            }
            for (; j < cnt; j++) a0 += pr[j] * Vd[(size_t)lst[j] * Dd];
            S.heads[bb][d] = ((a0 + a1) + (a2 + a3)) / S.sum[bb][h];
        }
        __syncthreads();

        // ---- Woc matvec: thread (bb,d); half smem, half L2 -----------------
        float mv = 0.f;
        if (t < Nn - 1) {
            const float* hr = S.heads[bb];
            float s0 = 0.f, s1 = 0.f;
            #pragma unroll 8
            for (int k = 0; k < WOC_SROWS; k += 2) {
                s0 += hr[k]     * S.wocs[(size_t)k * Dd + d];
                s1 += hr[k + 1] * S.wocs[(size_t)(k + 1) * Dd + d];
            }
            float g0 = 0.f, g1 = 0.f;
            const float* Wp = g_Woc + (size_t)WOC_SROWS * Dd + d;
            #pragma unroll 8
            for (int k = 0; k < Dd - WOC_SROWS; k += 2) {
                g0 += hr[WOC_SROWS + k]     * Wp[(size_t)k * Dd];
                g1 += hr[WOC_SROWS + k + 1] * Wp[(size_t)(k + 1) * Dd];
            }
            mv = (s0 + s1) + (g0 + g1);
        }

        {   // ---- logits: 8 warps per batch, 4 rows/iter --------------------
            const float4* h4 = (const float4*)S.heads[wb];
            float4 ha = h4[lane], hb = h4[lane + 32];
            const float* Lb = LKbase + (size_t)wb * Nn * Dd;
            const int* lst = S.list[wb];
            for (int j = wj0; j < cnt; j += 32) {
                const int j1 = j + 8, j2 = j + 16, j3 = j + 24;
                const bool v1 = (j1 < cnt), v2 = (j2 < cnt), v3 = (j3 < cnt);
                const float4* R0 = (const float4*)(Lb + (size_t)lst[j] * Dd);
                const float4* R1 = (const float4*)(Lb + (size_t)lst[v1 ? j1 : j] * Dd);
                const float4* R2 = (const float4*)(Lb + (size_t)lst[v2 ? j2 : j] * Dd);
                const float4* R3 = (const float4*)(Lb + (size_t)lst[v3 ? j3 : j] * Dd);
                float4 x0 = R0[lane], x1 = R0[lane + 32];
                float4 y0 = R1[lane], y1 = R1[lane + 32];
                float4 z0 = R2[lane], z1 = R2[lane + 32];
                float4 u0 = R3[lane], u1 = R3[lane + 32];
                float a = DOT4(x0, ha) + DOT4(x1, hb);
                float b = DOT4(y0, ha) + DOT4(y1, hb);
                float cq = DOT4(z0, ha) + DOT4(z1, hb);
                float dq = DOT4(u0, ha) + DOT4(u1, hb);
                #pragma unroll
                for (int o = 16; o; o >>= 1) {
                    a  += __shfl_xor_sync(0xffffffffu, a, o);
                    b  += __shfl_xor_sync(0xffffffffu, b, o);
                    cq += __shfl_xor_sync(0xffffffffu, cq, o);
                    dq += __shfl_xor_sync(0xffffffffu, dq, o);
                }
                if (lane == 0) {
                    S.ls[wb][j] = CLIPV * tanhf(a * INV_SQRT_D);
                    if (v1) S.ls[wb][j1] = CLIPV * tanhf(b  * INV_SQRT_D);
                    if (v2) S.ls[wb][j2] = CLIPV * tanhf(cq * INV_SQRT_D);
                    if (v3) S.ls[wb][j3] = CLIPV * tanhf(dq * INV_SQRT_D);
                }
            }
        }
        __syncthreads();

        // ---- argmax + log-softmax at selected: warps 0 (bb0) / 8 (bb1) ----
        if ((warp & 7) == 0) {
            const int sb = warp >> 3;
            float m = NEGV; int mj = 0;
            for (int j = lane; j < cnt; j += 32) {
                float v = S.ls[sb][j];
                if (v > m) { m = v; mj = j; }
            }
            #pragma unroll
            for (int o = 16; o; o >>= 1) {
                float vm = __shfl_xor_sync(0xffffffffu, m, o);
                int   vj = __shfl_xor_sync(0xffffffffu, mj, o);
                if (vm > m || (vm == m && vj < mj)) { m = vm; mj = vj; }
            }
            float s = 0.f;
            for (int j = lane; j < cnt; j += 32) s += expf(S.ls[sb][j] - m);
            #pragma unroll
            for (int o = 16; o; o >>= 1) s += __shfl_xor_sync(0xffffffffu, s, o);
            if (lane == 0) {
                int node = S.list[sb][mj];
                S.sel[sb] = node;
                ll += S.ls[sb][mj] - (m + logf(s));
                float cx = coords[((size_t)(b0 + sb) * Nn + node) * 2 + 0];
                float cy = coords[((size_t)(b0 + sb) * Nn + node) * 2 + 1];
                if (t == 0) { fx = cx; fy = cy; }
                else {
                    float dx = cx - px, dy = cy - py;
                    cost += sqrtf(dx * dx + dy * dy);
                }
                px = cx; py = cy;
                S.list[sb][mj] = S.list[sb][cnt - 1];
            }
        }
        if (tid == 0) S.cnt = cnt - 1;
        __syncthreads();

        if (t == 0) {   // fctx(bb,d) = E[b,first] @ Ws_top (heads as staging)
            S.heads[bb][d] = E[((size_t)(b0 + bb) * Nn + S.sel[bb]) * Dd + d];
            __syncthreads();
            float f = 0.f;
            #pragma unroll 8
            for (int k = 0; k < Dd; k++) f += S.heads[bb][k] * Ws[k * Dd + d];
            fctx = f;
            __syncthreads();
        }

        if (t < Nn - 1) {   // next raw query: mv + fctx + P[sel]
            S.q[bb][d] = fctx + mv +
                g_P[((size_t)(b0 + bb) * Nn + S.sel[bb]) * Dd + d];
            k4_fin_q(S, bb, d, mlp, W1, b1, W2, b2);
        }
    }

    if ((warp & 7) == 0 && lane == 0) {
        const int sb = warp >> 3;
        float dx = px - fx, dy = py - fy;
        cost += sqrtf(dx * dx + dy * dy);
        out[b0 + sb]      = cost;
        out[Bq + b0 + sb] = ll;
    }
}

// ---------------- launcher ---------------------------------------------------
extern "C" void kernel_launch(void* const* d_in, const int* in_sizes, int n_in,
                              void* d_out, int out_size)
{
    const float* coords = (const float*)d_in[0];
    const float* E      = (const float*)d_in[1];
    const float* Wk     = (const float*)d_in[2];
    const float* Wv     = (const float*)d_in[3];
    const float* Wlk    = (const float*)d_in[4];
    const float* Wo     = (const float*)d_in[5];
    const float* Wc     = (const float*)d_in[6];
    const float* Ws     = (const float*)d_in[7];
    const float* Wph    = (const float*)d_in[8];
    const float* W1     = (const float*)d_in[9];
    const float* b1     = (const float*)d_in[10];
    const float* W2     = (const float*)d_in[11];
    const float* b2     = (const float*)d_in[12];
    float* out = (float*)d_out;

    const int k4_smem = (int)sizeof(K4S);   // ~152KB -> 1 block/SM
    cudaFuncSetAttribute(k4_decode, cudaFuncAttributeMaxDynamicSharedMemorySize,
                         k4_smem);
    cudaFuncSetAttribute(k3t_mma, cudaFuncAttributeMaxDynamicSharedMemorySize,
                         K3T_SMEM);

    // 4 launches; k4 is the 4th (ncu capture slot)
    k1_weights<<<513, 256>>>(Wo, Wc, Wlk, W2, b2);
    k_split<<<9216, 256>>>(E, Wk, Wv, Ws);
    {
        dim3 g3(ROWS_TOTAL / 128, 2, 4);
        k3t_mma<<<g3, 256, K3T_SMEM>>>();
    }
    k4_decode<<<Bq / NB, 512, k4_smem>>>(E, coords, Wc, Ws, Wph, W1, b1, W2, b2, out);
}

// round 17
// speedup vs baseline: 1.3260x; 1.3260x over previous
#include <cuda_runtime.h>
#include <cuda_fp16.h>
#include <cstdint>

// Problem constants
#define Bq   1024
#define Nn   128
#define Dd   256
#define Hh   8
#define NB   2
#define NEGV (-1e9f)
#define CLIPV 10.0f
#define INV_SQRT_DH 0.17677669529663687f  // 1/sqrt(32)
#define INV_SQRT_D  0.0625f               // 1/sqrt(256)

#define ROWS_TOTAL (Bq * Nn)              // 131072
#define WSCALE     16.0f                  // W pre-scale (exact pow2)
#define WUNSCALE   0.0625f                // 1/16
#define WOC_SROWS  64                     // Woc rows cached in smem (64KB)

// ---------------- scratch (device globals; no cudaMalloc allowed) ----------
__device__ float g_K   [Bq * Nn * Dd];   // [b][n][d]  (E@Wk)
__device__ float g_V   [Bq * Nn * Dd];   // [b][n][d]  (E@Wv)
__device__ float g_LK2 [Bq * Nn * Dd];   // [b][n][d]  (E@(Wlk@Wo^T))
__device__ float g_P   [Bq * Nn * Dd];   // [b][n][d]  (E@Ws_bot)
__device__ float g_Woc [Dd * Dd];        // Wo@Wc
__device__ float g_Wlk2[Dd * Dd];        // Wlk@Wo^T
__device__ int   g_mlp;                  // 1 if (W2,b2) nonzero -> general path

// fp16 2-way splits (x ~= h0+h1 to ~2^-22)
__device__ __half g_Es[2][ROWS_TOTAL * Dd];     // E splits
__device__ __half g_Wt[2][4][Dd * Dd];          // (16*W)^T splits [s][w][n][k]

// ================= helpers ==================================================
__device__ __forceinline__ uint32_t smem_u32(const void* p) {
    uint32_t a;
    asm("{ .reg .u64 t; cvta.to.shared.u64 t, %1; cvt.u32.u64 %0, t; }"
        : "=r"(a) : "l"(p));
    return a;
}
__device__ __forceinline__ void ldsm_x4(uint32_t* r, uint32_t addr) {
    asm volatile("ldmatrix.sync.aligned.m8n8.x4.shared.b16 {%0,%1,%2,%3}, [%4];"
        : "=r"(r[0]), "=r"(r[1]), "=r"(r[2]), "=r"(r[3]) : "r"(addr));
}
__device__ __forceinline__ void mma_fp16(float* c, const uint32_t* a, const uint32_t* b) {
    asm volatile("mma.sync.aligned.m16n8k16.row.col.f32.f16.f16.f32 "
        "{%0,%1,%2,%3}, {%4,%5,%6,%7}, {%8,%9}, {%0,%1,%2,%3};"
        : "+f"(c[0]), "+f"(c[1]), "+f"(c[2]), "+f"(c[3])
        : "r"(a[0]), "r"(a[1]), "r"(a[2]), "r"(a[3]), "r"(b[0]), "r"(b[1]));
}
__device__ __forceinline__ void cp_async16(uint32_t dst, const void* src) {
    asm volatile("cp.async.cg.shared.global [%0], [%1], 16;"
                 :: "r"(dst), "l"(src) : "memory");
}
#define CP_COMMIT() asm volatile("cp.async.commit_group;" ::: "memory")
#define CP_WAIT0()  asm volatile("cp.async.wait_group 0;" ::: "memory")

#define K3_ABUF(p) ((p) * 16384)
#define K3_BBUF(p) (32768 + (p) * 16384)
#define K3T_SMEM   65536

#define DOT4(u, v) ((u).x * (v).x + (u).y * (v).y + (u).z * (v).z + (u).w * (v).w)

// ---------------- k1: Woc = Wo@Wc ; Wlk2 = Wlk@Wo^T ; mlp-detect -----------
__global__ void k1_weights(const float* __restrict__ Wo,
                           const float* __restrict__ Wc,
                           const float* __restrict__ Wlk,
                           const float* __restrict__ W2,
                           const float* __restrict__ b2)
{
    int bid = blockIdx.x;
    int d = threadIdx.x;
    if (bid < 256) {               // Woc row bid
        float acc = 0.f;
        #pragma unroll 8
        for (int j = 0; j < Dd; j++) acc += Wo[bid * Dd + j] * Wc[j * Dd + d];
        g_Woc[bid * Dd + d] = acc;
    } else if (bid < 512) {        // Wlk2 row m: sum_j Wlk[m][j] * Wo[d][j]
        int m = bid - 256;
        __shared__ float lr[Dd];
        lr[d] = Wlk[m * Dd + d];
        __syncthreads();
        const float* Wod = Wo + (size_t)d * Dd;
        float a0 = 0.f, a1 = 0.f;
        #pragma unroll 8
        for (int j = 0; j < Dd; j += 2) {
            a0 += lr[j]     * Wod[j];
            a1 += lr[j + 1] * Wod[j + 1];
        }
        g_Wlk2[m * Dd + d] = a0 + a1;
    } else {                       // mlp-nonzero detect
        __shared__ int any;
        if (d == 0) any = 0;
        __syncthreads();
        int loc = 0;
        for (int i = d; i < Dd * Dd; i += blockDim.x) loc |= (W2[i] != 0.0f);
        loc |= (b2[d] != 0.0f);
        if (loc) atomicOr(&any, 1);
        __syncthreads();
        if (d == 0) g_mlp = any;
    }
}

// ---------------- k_split: fused E-split + W-split ---------------------------
__global__ void k_split(const float* __restrict__ E,
                        const float* __restrict__ Wk,
                        const float* __restrict__ Wv,
                        const float* __restrict__ Ws)
{
    const int bid = blockIdx.x;
    if (bid < 8192) {
        const size_t total = (size_t)ROWS_TOTAL * Dd;
        const size_t stride = (size_t)8192 * blockDim.x;
        for (size_t i = (size_t)bid * blockDim.x + threadIdx.x; i < total; i += stride) {
            float x = E[i];
            __half h0 = __float2half_rn(x);
            float r = x - __half2float(h0);
            __half h1 = __float2half_rn(r);
            g_Es[0][i] = h0; g_Es[1][i] = h1;
        }
    } else {
        const int idx = bid - 8192;
        const int w = idx & 3, n = idx >> 2, k = threadIdx.x;
        const float* src;
        if      (w == 0) src = Wk;
        else if (w == 1) src = Wv;
        else if (w == 2) src = g_Wlk2;
        else             src = Ws + Dd * Dd;
        float x = src[k * Dd + n] * WSCALE;
        __half h0 = __float2half_rn(x);
        float r = x - __half2float(h0);
        __half h1 = __float2half_rn(r);
        g_Wt[0][w][n * Dd + k] = h0;
        g_Wt[1][w][n * Dd + k] = h1;
    }
}

// ---------------- k3t: mma.sync fp16-2split GEMM, cp.async pipelined --------
__global__ void __launch_bounds__(256, 2) k3t_mma()
{
    extern __shared__ char smem[];
    const uint32_t sbase = smem_u32(smem);
    const int tid = threadIdx.x;
    const int warp = tid >> 5, lane = tid & 31;
    const int rowbase = blockIdx.x * 128;
    const int nbase   = blockIdx.y * 128;
    const int w       = blockIdx.z;

    float* out;
    if      (w == 0) out = g_K;
    else if (w == 1) out = g_V;
    else if (w == 2) out = g_LK2;
    else             out = g_P;

    const int wm = warp & 3;
    const int wn = warp >> 2;

    float acc[2][8][4] = {};

    uint32_t st_dst[8];
    const __half* st_src[8];
    #pragma unroll
    for (int it = 0; it < 8; it++) {
        int i = tid + it * 256;
        int reg = i >> 10, s = (i >> 9) & 1, row = (i >> 2) & 127, q = i & 3;
        uint32_t off = (uint32_t)(s * 8192 + row * 64 + ((q * 16) ^ ((row & 6) << 3)));
        if (reg == 0) {
            st_dst[it] = off;
            st_src[it] = &g_Es[s][(size_t)(rowbase + row) * Dd + q * 8];
        } else {
            st_dst[it] = 32768u + off;
            st_src[it] = &g_Wt[s][w][(size_t)(nbase + row) * Dd + q * 8];
        }
    }

    uint32_t a_off[2], a_mask[2];
    #pragma unroll
    for (int mb = 0; mb < 2; mb++) {
        int row = wm * 32 + mb * 16 + (lane & 15);
        a_off[mb]  = (uint32_t)(row * 64);
        a_mask[mb] = (uint32_t)(((row & 6) << 3) ^ ((lane >> 4) * 16));
    }
    uint32_t b_off[4], b_mask[4];
    #pragma unroll
    for (int p = 0; p < 4; p++) {
        int pr = lane >> 3;
        int nrow = wn * 64 + p * 16 + ((pr >> 1) << 3) + (lane & 7);
        b_off[p]  = (uint32_t)(nrow * 64);
        b_mask[p] = (uint32_t)(((nrow & 6) << 3) ^ ((pr & 1) * 16));
    }

    {
        const uint32_t abase = sbase + K3_ABUF(0);
        #pragma unroll
        for (int it = 0; it < 8; it++)
            cp_async16(abase + st_dst[it], st_src[it]);
        CP_COMMIT();
    }

    for (int c = 0; c < 8; c++) {
        CP_WAIT0();
        __syncthreads();

        if (c + 1 < 8) {
            const uint32_t abase = sbase + K3_ABUF((c + 1) & 1);
            const int kadv = (c + 1) * 32;
            #pragma unroll
            for (int it = 0; it < 8; it++)
                cp_async16(abase + st_dst[it], st_src[it] + kadv);
            CP_COMMIT();
        }

        const uint32_t Ab = sbase + K3_ABUF(c & 1);
        const uint32_t Bb = sbase + K3_BBUF(c & 1);

        #pragma unroll
        for (int ks = 0; ks < 2; ks++) {
            const uint32_t kx = (uint32_t)(ks * 32);
            uint32_t af[2][2][4];
            #pragma unroll
            for (int s = 0; s < 2; s++)
                #pragma unroll
                for (int mb = 0; mb < 2; mb++)
                    ldsm_x4(af[s][mb], Ab + s * 8192 + a_off[mb] + (kx ^ a_mask[mb]));
            #pragma unroll
            for (int p = 0; p < 4; p++) {
                uint32_t b0[4];
                ldsm_x4(b0, Bb + b_off[p] + (kx ^ b_mask[p]));
                #pragma unroll
                for (int sa = 0; sa < 2; sa++) {
                    mma_fp16(acc[0][2 * p],     af[sa][0], b0 + 0);
                    mma_fp16(acc[0][2 * p + 1], af[sa][0], b0 + 2);
                    mma_fp16(acc[1][2 * p],     af[sa][1], b0 + 0);
                    mma_fp16(acc[1][2 * p + 1], af[sa][1], b0 + 2);
                }
                uint32_t b1[4];
                ldsm_x4(b1, Bb + 8192 + b_off[p] + (kx ^ b_mask[p]));
                mma_fp16(acc[0][2 * p],     af[0][0], b1 + 0);
                mma_fp16(acc[0][2 * p + 1], af[0][0], b1 + 2);
                mma_fp16(acc[1][2 * p],     af[0][1], b1 + 0);
                mma_fp16(acc[1][2 * p + 1], af[0][1], b1 + 2);
            }
        }
        __syncthreads();
    }

    const int r0 = rowbase + wm * 32 + (lane >> 2);
    const int c0 = nbase + wn * 64 + (lane & 3) * 2;
    #pragma unroll
    for (int mb = 0; mb < 2; mb++)
        #pragma unroll
        for (int nb = 0; nb < 8; nb++) {
            float2 lo = make_float2(acc[mb][nb][0] * WUNSCALE, acc[mb][nb][1] * WUNSCALE);
            float2 hi = make_float2(acc[mb][nb][2] * WUNSCALE, acc[mb][nb][3] * WUNSCALE);
            *(float2*)(out + (size_t)(r0 + mb * 16)     * Dd + c0 + nb * 8) = lo;
            *(float2*)(out + (size_t)(r0 + mb * 16 + 8) * Dd + c0 + nb * 8) = hi;
        }
}

// ---------------- k4: persistent decode, 512 threads, 2 blocks/SM -----------
// 32 warps/SM (latency hiding of R14) + 1.73 waves with per-step chip touch
// ~115MB <= L2 (stream rows hit L2 across steps). 64 Woc rows cached in smem.
// Thread (bb = tid>>8, d = tid&255) owns one (batch, dim).
struct K4S {
    float q[NB][Dd];
    float heads[NB][Dd];          // also staging (q0-mean / t==0 E rows)
    float cc[NB][Nn][9];          // compat; reused as MLP scratch
    float pp[NB][Hh][Nn + 4];
    float ls[NB][Nn];
    int   list[NB][Nn];
    float sum[NB][Hh];
    int   sel[NB];
    int   cnt;
    float wocs[WOC_SROWS * Dd];   // Woc rows [0,64) in smem (64KB)
};

__device__ __forceinline__ void k4_fin_q(K4S& S, int bb, int d, int mlp,
                                         const float* __restrict__ W1,
                                         const float* __restrict__ b1,
                                         const float* __restrict__ W2,
                                         const float* __restrict__ b2)
{
    if (mlp) {
        float* hid = &S.cc[0][0][0];
        __syncthreads();
        float m1 = b1[d];
        #pragma unroll 8
        for (int k = 0; k < Dd; k++) m1 += S.q[bb][k] * W1[k * Dd + d];
        hid[bb * Dd + d] = fmaxf(m1, 0.0f);
        __syncthreads();
        float m2 = b2[d];
        #pragma unroll 8
        for (int k = 0; k < Dd; k++) m2 += hid[bb * Dd + k] * W2[k * Dd + d];
        __syncthreads();
        S.q[bb][d] = (S.q[bb][d] + m2) * INV_SQRT_DH;
    } else {
        S.q[bb][d] *= INV_SQRT_DH;
    }
    __syncthreads();
}

__global__ void __launch_bounds__(512, 2) k4_decode(const float* __restrict__ E,
                                                    const float* __restrict__ coords,
                                                    const float* __restrict__ Wc,
                                                    const float* __restrict__ Ws,
                                                    const float* __restrict__ Wph,
                                                    const float* __restrict__ W1,
                                                    const float* __restrict__ b1,
                                                    const float* __restrict__ W2,
                                                    const float* __restrict__ b2,
                                                    float* __restrict__ out)
{
    extern __shared__ char smem_raw[];
    K4S& S = *(K4S*)smem_raw;

    const int b0 = blockIdx.x * NB;
    const int tid = threadIdx.x;            // 0..511
    const int warp = tid >> 5, lane = tid & 31;
    const int wb  = warp >> 3;               // batch for row-dot phases
    const int wj0 = warp & 7;                // row start, stride 8
    const int bb  = tid >> 8;                // batch this thread owns
    const int d   = tid & 255;               // dim this thread owns
    const int mlp = g_mlp;

    // load Woc rows [0,WOC_SROWS) into smem (one-time)
    for (int i = tid; i < WOC_SROWS * Dd; i += 512) S.wocs[i] = g_Woc[i];

    if (tid < Nn) {
        S.list[0][tid] = tid;
        S.list[1][tid] = tid;
    }
    if (tid == 0) S.cnt = Nn;

    // ---- prologue: q0 = mean_n(E)@Wc + Wph@Ws ------------------------------
    {
        float pcv = 0.f;
        #pragma unroll 8
        for (int k = 0; k < 2 * Dd; k++) pcv += Wph[k] * Ws[k * Dd + d];
        float s = 0.f;
        const float* Eb = E + (size_t)(b0 + bb) * Nn * Dd + d;
        #pragma unroll 8
        for (int n = 0; n < Nn; n++) s += Eb[n * Dd];
        S.heads[bb][d] = s * (1.0f / Nn);
        __syncthreads();
        float acc = pcv;
        #pragma unroll 8
        for (int k = 0; k < Dd; k++) acc += S.heads[bb][k] * Wc[k * Dd + d];
        __syncthreads();
        S.q[bb][d] = acc;
    }
    k4_fin_q(S, bb, d, mlp, W1, b1, W2, b2);

    const float* Kbase  = g_K   + (size_t)b0 * Nn * Dd;
    const float* Vbase  = g_V   + (size_t)b0 * Nn * Dd;
    const float* LKbase = g_LK2 + (size_t)b0 * Nn * Dd;

    float ll = 0.f, cost = 0.f;             // lane0 of warps 0 and 8
    float fx = 0.f, fy = 0.f, px = 0.f, py = 0.f;
    float fctx = 0.f;                        // per-thread (bb,d)

    for (int t = 0; t < Nn; t++) {
        const int cnt = S.cnt;

        {   // ---- compat: 8 warps per batch, 4 rows/iter --------------------
            const float4* q4 = (const float4*)S.q[wb];
            float4 qa = q4[lane], qb = q4[lane + 32];
            const float* Kb = Kbase + (size_t)wb * Nn * Dd;
            const int* lst = S.list[wb];
            for (int j = wj0; j < cnt; j += 32) {
                const int j1 = j + 8, j2 = j + 16, j3 = j + 24;
                const bool v1 = (j1 < cnt), v2 = (j2 < cnt), v3 = (j3 < cnt);
                const float4* R0 = (const float4*)(Kb + (size_t)lst[j] * Dd);
                const float4* R1 = (const float4*)(Kb + (size_t)lst[v1 ? j1 : j] * Dd);
                const float4* R2 = (const float4*)(Kb + (size_t)lst[v2 ? j2 : j] * Dd);
                const float4* R3 = (const float4*)(Kb + (size_t)lst[v3 ? j3 : j] * Dd);
                float4 x0 = R0[lane], x1 = R0[lane + 32];
                float4 y0 = R1[lane], y1 = R1[lane + 32];
                float4 z0 = R2[lane], z1 = R2[lane + 32];
                float4 u0 = R3[lane], u1 = R3[lane + 32];
                float alo = DOT4(x0, qa), ahi = DOT4(x1, qb);
                float blo = DOT4(y0, qa), bhi = DOT4(y1, qb);
                float clo = DOT4(z0, qa), chi = DOT4(z1, qb);
                float dlo = DOT4(u0, qa), dhi = DOT4(u1, qb);
                #pragma unroll
                for (int o = 1; o < 8; o <<= 1) {
                    alo += __shfl_xor_sync(0xffffffffu, alo, o);
                    ahi += __shfl_xor_sync(0xffffffffu, ahi, o);
                    blo += __shfl_xor_sync(0xffffffffu, blo, o);
                    bhi += __shfl_xor_sync(0xffffffffu, bhi, o);
                    clo += __shfl_xor_sync(0xffffffffu, clo, o);
                    chi += __shfl_xor_sync(0xffffffffu, chi, o);
                    dlo += __shfl_xor_sync(0xffffffffu, dlo, o);
                    dhi += __shfl_xor_sync(0xffffffffu, dhi, o);
                }
                if ((lane & 7) == 0) {
                    int hg = lane >> 3;
                    S.cc[wb][j][hg]     = alo;
                    S.cc[wb][j][4 + hg] = ahi;
                    if (v1) { S.cc[wb][j1][hg] = blo; S.cc[wb][j1][4 + hg] = bhi; }
                    if (v2) { S.cc[wb][j2][hg] = clo; S.cc[wb][j2][4 + hg] = chi; }
                    if (v3) { S.cc[wb][j3][hg] = dlo; S.cc[wb][j3][4 + hg] = dhi; }
                }
            }
        }
        __syncthreads();

        {   // ---- softmax: warp = (bb, h), single pass ----------------------
            const int sb = warp >> 3, h = warp & 7;
            float m = NEGV;
            for (int j = lane; j < cnt; j += 32) m = fmaxf(m, S.cc[sb][j][h]);
            #pragma unroll
            for (int o = 16; o; o >>= 1)
                m = fmaxf(m, __shfl_xor_sync(0xffffffffu, m, o));
            float s = 0.f;
            for (int j = lane; j < cnt; j += 32) {
                float e = expf(S.cc[sb][j][h] - m);
                S.pp[sb][h][j] = e;
                s += e;
            }
            #pragma unroll
            for (int o = 16; o; o >>= 1) s += __shfl_xor_sync(0xffffffffu, s, o);
            if (lane == 0) S.sum[sb][h] = s;
        }
        __syncthreads();

        {   // ---- heads: thread (bb,d), 4 accumulators ----------------------
            const int h = d >> 5;
            float a0 = 0.f, a1 = 0.f, a2 = 0.f, a3 = 0.f;
            const float* Vd = Vbase + (size_t)bb * Nn * Dd + d;
            const int* lst = S.list[bb];
            const float* pr = S.pp[bb][h];
            int j = 0;
            for (; j + 4 <= cnt; j += 4) {
                a0 += pr[j]     * Vd[(size_t)lst[j]     * Dd];
                a1 += pr[j + 1] * Vd[(size_t)lst[j + 1] * Dd];
                a2 += pr[j + 2] * Vd[(size_t)lst[j + 2] * Dd];
                a3 += pr[j + 3] * Vd[(size_t)lst[j + 3] * Dd];
            }
            for (; j < cnt; j++) a0 += pr[j] * Vd[(size_t)lst[j] * Dd];
            S.heads[bb][d] = ((a0 + a1) + (a2 + a3)) / S.sum[bb][h];
        }
        __syncthreads();

        // ---- Woc matvec: thread (bb,d); 64 rows smem, rest L2 --------------
        float mv = 0.f;
        if (t < Nn - 1) {
            const float* hr = S.heads[bb];
            float s0 = 0.f, s1 = 0.f;
            #pragma unroll 8
            for (int k = 0; k < WOC_SROWS; k += 2) {
                s0 += hr[k]     * S.wocs[(size_t)k * Dd + d];
                s1 += hr[k + 1] * S.wocs[(size_t)(k + 1) * Dd + d];
            }
            float g0 = 0.f, g1 = 0.f;
            const float* Wp = g_Woc + (size_t)WOC_SROWS * Dd + d;
            #pragma unroll 8
            for (int k = 0; k < Dd - WOC_SROWS; k += 2) {
                g0 += hr[WOC_SROWS + k]     * Wp[(size_t)k * Dd];
                g1 += hr[WOC_SROWS + k + 1] * Wp[(size_t)(k + 1) * Dd];
            }
            mv = (s0 + s1) + (g0 + g1);
        }

        {   // ---- logits: 8 warps per batch, 4 rows/iter --------------------
            const float4* h4 = (const float4*)S.heads[wb];
            float4 ha = h4[lane], hb = h4[lane + 32];
            const float* Lb = LKbase + (size_t)wb * Nn * Dd;
            const int* lst = S.list[wb];
            for (int j = wj0; j < cnt; j += 32) {
                const int j1 = j + 8, j2 = j + 16, j3 = j + 24;
                const bool v1 = (j1 < cnt), v2 = (j2 < cnt), v3 = (j3 < cnt);
                const float4* R0 = (const float4*)(Lb + (size_t)lst[j] * Dd);
                const float4* R1 = (const float4*)(Lb + (size_t)lst[v1 ? j1 : j] * Dd);
                const float4* R2 = (const float4*)(Lb + (size_t)lst[v2 ? j2 : j] * Dd);
                const float4* R3 = (const float4*)(Lb + (size_t)lst[v3 ? j3 : j] * Dd);
                float4 x0 = R0[lane], x1 = R0[lane + 32];
                float4 y0 = R1[lane], y1 = R1[lane + 32];
                float4 z0 = R2[lane], z1 = R2[lane + 32];
                float4 u0 = R3[lane], u1 = R3[lane + 32];
                float a = DOT4(x0, ha) + DOT4(x1, hb);
                float b = DOT4(y0, ha) + DOT4(y1, hb);
                float cq = DOT4(z0, ha) + DOT4(z1, hb);
                float dq = DOT4(u0, ha) + DOT4(u1, hb);
                #pragma unroll
                for (int o = 16; o; o >>= 1) {
                    a  += __shfl_xor_sync(0xffffffffu, a, o);
                    b  += __shfl_xor_sync(0xffffffffu, b, o);
                    cq += __shfl_xor_sync(0xffffffffu, cq, o);
                    dq += __shfl_xor_sync(0xffffffffu, dq, o);
                }
                if (lane == 0) {
                    S.ls[wb][j] = CLIPV * tanhf(a * INV_SQRT_D);
                    if (v1) S.ls[wb][j1] = CLIPV * tanhf(b  * INV_SQRT_D);
                    if (v2) S.ls[wb][j2] = CLIPV * tanhf(cq * INV_SQRT_D);
                    if (v3) S.ls[wb][j3] = CLIPV * tanhf(dq * INV_SQRT_D);
                }
            }
        }
        __syncthreads();

        // ---- argmax + log-softmax at selected: warps 0 (bb0) / 8 (bb1) ----
        if ((warp & 7) == 0) {
            const int sb = warp >> 3;
            float m = NEGV; int mj = 0;
            for (int j = lane; j < cnt; j += 32) {
                float v = S.ls[sb][j];
                if (v > m) { m = v; mj = j; }
            }
            #pragma unroll
            for (int o = 16; o; o >>= 1) {
                float vm = __shfl_xor_sync(0xffffffffu, m, o);
                int   vj = __shfl_xor_sync(0xffffffffu, mj, o);
                if (vm > m || (vm == m && vj < mj)) { m = vm; mj = vj; }
            }
            float s = 0.f;
            for (int j = lane; j < cnt; j += 32) s += expf(S.ls[sb][j] - m);
            #pragma unroll
            for (int o = 16; o; o >>= 1) s += __shfl_xor_sync(0xffffffffu, s, o);
            if (lane == 0) {
                int node = S.list[sb][mj];
                S.sel[sb] = node;
                ll += S.ls[sb][mj] - (m + logf(s));
                float cx = coords[((size_t)(b0 + sb) * Nn + node) * 2 + 0];
                float cy = coords[((size_t)(b0 + sb) * Nn + node) * 2 + 1];
                if (t == 0) { fx = cx; fy = cy; }
                else {
                    float dx = cx - px, dy = cy - py;
                    cost += sqrtf(dx * dx + dy * dy);
                }
                px = cx; py = cy;
                S.list[sb][mj] = S.list[sb][cnt - 1];
            }
        }
        if (tid == 0) S.cnt = cnt - 1;
        __syncthreads();

        if (t == 0) {   // fctx(bb,d) = E[b,first] @ Ws_top (heads as staging)
            S.heads[bb][d] = E[((size_t)(b0 + bb) * Nn + S.sel[bb]) * Dd + d];
            __syncthreads();
            float f = 0.f;
            #pragma unroll 8
            for (int k = 0; k < Dd; k++) f += S.heads[bb][k] * Ws[k * Dd + d];
            fctx = f;
            __syncthreads();
        }

        if (t < Nn - 1) {   // next raw query: mv + fctx + P[sel]
            S.q[bb][d] = fctx + mv +
                g_P[((size_t)(b0 + bb) * Nn + S.sel[bb]) * Dd + d];
            k4_fin_q(S, bb, d, mlp, W1, b1, W2, b2);
        }
    }

    if ((warp & 7) == 0 && lane == 0) {
        const int sb = warp >> 3;
        float dx = px - fx, dy = py - fy;
        cost += sqrtf(dx * dx + dy * dy);
        out[b0 + sb]      = cost;
        out[Bq + b0 + sb] = ll;
    }
}

// ---------------- launcher ---------------------------------------------------
extern "C" void kernel_launch(void* const* d_in, const int* in_sizes, int n_in,
                              void* d_out, int out_size)
{
    const float* coords = (const float*)d_in[0];
    const float* E      = (const float*)d_in[1];
    const float* Wk     = (const float*)d_in[2];
    const float* Wv     = (const float*)d_in[3];
    const float* Wlk    = (const float*)d_in[4];
    const float* Wo     = (const float*)d_in[5];
    const float* Wc     = (const float*)d_in[6];
    const float* Ws     = (const float*)d_in[7];
    const float* Wph    = (const float*)d_in[8];
    const float* W1     = (const float*)d_in[9];
    const float* b1     = (const float*)d_in[10];
    const float* W2     = (const float*)d_in[11];
    const float* b2     = (const float*)d_in[12];
    float* out = (float*)d_out;

    const int k4_smem = (int)sizeof(K4S);   // ~89KB -> 2 blocks/SM
    cudaFuncSetAttribute(k4_decode, cudaFuncAttributeMaxDynamicSharedMemorySize,
                         k4_smem);
    cudaFuncSetAttribute(k3t_mma, cudaFuncAttributeMaxDynamicSharedMemorySize,
                         K3T_SMEM);

    // 4 launches; k4 is the 4th (ncu capture slot)
    k1_weights<<<513, 256>>>(Wo, Wc, Wlk, W2, b2);
    k_split<<<9216, 256>>>(E, Wk, Wv, Ws);
    {
        dim3 g3(ROWS_TOTAL / 128, 2, 4);
        k3t_mma<<<g3, 256, K3T_SMEM>>>();
    }
    k4_decode<<<Bq / NB, 512, k4_smem>>>(E, coords, Wc, Ws, Wph, W1, b1, W2, b2, out);
}